// round 1
// baseline (speedup 1.0000x reference)
#include <cuda_runtime.h>

// Problem collapse:
//   K rows identical per batch  -> scores constant along m -> softmax uniform 1/N
//   V rows identical per batch  -> attended[b,n,:] == V[b,:] = g[b]@Wv + bv
//   out[b,n,:] = (g[b]@Wv + bv) @ Wo + bo      (broadcast along n)
//
// Shapes: B=8, N=4096, LOCAL=512, GLOBAL=128, HIDDEN=256.
// Inputs (metadata order): x, g, Wq, bq, Wk, bk, Wv, bv, Wo, bo

#define B_SZ      8
#define N_PTS     4096
#define LOCAL_D   512
#define GLOBAL_D  128
#define HIDDEN_D  256

// Scratch for the 8 per-batch output vectors (8 x 512 fp32). Static device
// global -> no allocation, graph-capture safe.
__device__ float g_rowvec[B_SZ * LOCAL_D];

// ---------------------------------------------------------------------------
// Kernel 1: per-batch  v = g@Wv + bv  (256)  ->  o = v@Wo + bo  (512)
// grid = 8 (one block per batch), block = 512 threads.
// ---------------------------------------------------------------------------
__global__ void __launch_bounds__(512, 1)
compute_row_vectors(const float* __restrict__ g,
                    const float* __restrict__ Wv,  // [128, 256]
                    const float* __restrict__ bv,  // [256]
                    const float* __restrict__ Wo,  // [256, 512]
                    const float* __restrict__ bo)  // [512]
{
    __shared__ float sg[GLOBAL_D];
    __shared__ float sv[HIDDEN_D];

    const int b = blockIdx.x;
    const int t = threadIdx.x;

    if (t < GLOBAL_D) sg[t] = g[b * GLOBAL_D + t];
    __syncthreads();

    if (t < HIDDEN_D) {
        float acc = bv[t];
        #pragma unroll 8
        for (int k = 0; k < GLOBAL_D; ++k)
            acc += sg[k] * Wv[k * HIDDEN_D + t];
        sv[t] = acc;
    }
    __syncthreads();

    float acc = bo[t];
    #pragma unroll 8
    for (int h = 0; h < HIDDEN_D; ++h)
        acc += sv[h] * Wo[h * LOCAL_D + t];
    g_rowvec[b * LOCAL_D + t] = acc;
}

// ---------------------------------------------------------------------------
// Kernel 2: broadcast g_rowvec[b,:] along N into d_out.
// One float4 store per thread. Total float4s = 8*4096*512/4 = 4,194,304.
// Row has 128 float4s; idx layout: b = idx>>19, j = idx&127.
// ---------------------------------------------------------------------------
__global__ void __launch_bounds__(256)
broadcast_rows(float4* __restrict__ out)
{
    const unsigned idx = blockIdx.x * 256u + threadIdx.x;
    const unsigned j = idx & 127u;        // float4 within the 512-float row
    const unsigned b = idx >> 19;         // idx / (4096*128)
    const float4* s4 = reinterpret_cast<const float4*>(g_rowvec);
    out[idx] = __ldg(&s4[b * 128u + j]);
}

// ---------------------------------------------------------------------------
extern "C" void kernel_launch(void* const* d_in, const int* in_sizes, int n_in,
                              void* d_out, int out_size)
{
    const float* g  = (const float*)d_in[1];
    const float* Wv = (const float*)d_in[6];
    const float* bv = (const float*)d_in[7];
    const float* Wo = (const float*)d_in[8];
    const float* bo = (const float*)d_in[9];
    float* out = (float*)d_out;

    compute_row_vectors<<<B_SZ, 512>>>(g, Wv, bv, Wo, bo);

    const unsigned total4 = (B_SZ * N_PTS * LOCAL_D) / 4;   // 4,194,304
    broadcast_rows<<<total4 / 256, 256>>>(reinterpret_cast<float4*>(out));
}

// round 2
// speedup vs baseline: 1.3816x; 1.3816x over previous
#include <cuda_runtime.h>

// out[b,n,:] = ((g[b]@Wv + bv) @ Wo + bo)  broadcast along n   (see R1 notes)
// B=8, N=4096, LOCAL=512, GLOBAL=128, HIDDEN=256.
// Inputs: x, g, Wq, bq, Wk, bk, Wv, bv, Wo, bo

#define B_SZ      8
#define N_PTS     4096
#define LOCAL_D   512
#define GLOBAL_D  128
#define HIDDEN_D  256

__device__ float4 g_rowvec4[B_SZ * (LOCAL_D / 4)];   // 8 x 128 float4

// ---------------------------------------------------------------------------
// Kernel 1: per batch  v = g@Wv + bv (256), then o = v@Wo + bo (512).
// 8 blocks x 512 threads. All loads are float4; reduction dim split across
// threads, combined through smem.
// ---------------------------------------------------------------------------
__global__ void __launch_bounds__(512, 1)
compute_row_vectors(const float* __restrict__ g,
                    const float* __restrict__ Wv,  // [128, 256]
                    const float* __restrict__ bv,  // [256]
                    const float* __restrict__ Wo,  // [256, 512]
                    const float* __restrict__ bo)  // [512]
{
    __shared__ float  sg[GLOBAL_D];
    __shared__ float4 part[512];          // reused by both stages (8 KB)
    __shared__ float  sv[HIDDEN_D];

    const int b = blockIdx.x;
    const int t = threadIdx.x;

    if (t < GLOBAL_D) sg[t] = g[b * GLOBAL_D + t];
    __syncthreads();

    // ---- Stage A: v[h] = sum_k g[k] * Wv[k][h], h in float4 groups ----
    // thread = (ks in 0..7) * 64 + h4 in 0..63 ; each ks covers 16 k-values.
    {
        const int h4 = t & 63;
        const int ks = t >> 6;
        const float4* Wv4 = reinterpret_cast<const float4*>(Wv);  // row stride 64
        float4 acc = make_float4(0.f, 0.f, 0.f, 0.f);
        #pragma unroll
        for (int i = 0; i < 16; ++i) {
            const int k = ks * 16 + i;
            const float gk = sg[k];
            const float4 w = Wv4[k * 64 + h4];
            acc.x += gk * w.x; acc.y += gk * w.y;
            acc.z += gk * w.z; acc.w += gk * w.w;
        }
        part[ks * 64 + h4] = acc;
    }
    __syncthreads();

    if (t < 64) {
        float4 s = make_float4(0.f, 0.f, 0.f, 0.f);
        #pragma unroll
        for (int ks = 0; ks < 8; ++ks) {
            const float4 p = part[ks * 64 + t];
            s.x += p.x; s.y += p.y; s.z += p.z; s.w += p.w;
        }
        const float4 bv4 = reinterpret_cast<const float4*>(bv)[t];
        sv[4*t + 0] = s.x + bv4.x;
        sv[4*t + 1] = s.y + bv4.y;
        sv[4*t + 2] = s.z + bv4.z;
        sv[4*t + 3] = s.w + bv4.w;
    }
    __syncthreads();

    // ---- Stage B: o[u] = sum_h sv[h] * Wo[h][u], u in float4 groups ----
    // thread = (hs in 0..3) * 128 + t4 in 0..127 ; each hs covers 64 h-values.
    {
        const int t4 = t & 127;
        const int hs = t >> 7;
        const float4* Wo4 = reinterpret_cast<const float4*>(Wo);  // row stride 128
        float4 acc = make_float4(0.f, 0.f, 0.f, 0.f);
        #pragma unroll 8
        for (int i = 0; i < 64; ++i) {
            const int h = hs * 64 + i;
            const float vh = sv[h];
            const float4 w = Wo4[h * 128 + t4];
            acc.x += vh * w.x; acc.y += vh * w.y;
            acc.z += vh * w.z; acc.w += vh * w.w;
        }
        part[hs * 128 + t4] = acc;
    }
    __syncthreads();

    if (t < 128) {
        float4 s = make_float4(0.f, 0.f, 0.f, 0.f);
        #pragma unroll
        for (int hs = 0; hs < 4; ++hs) {
            const float4 p = part[hs * 128 + t];
            s.x += p.x; s.y += p.y; s.z += p.z; s.w += p.w;
        }
        const float4 bo4 = reinterpret_cast<const float4*>(bo)[t];
        s.x += bo4.x; s.y += bo4.y; s.z += bo4.z; s.w += bo4.w;
        g_rowvec4[b * 128 + t] = s;
    }
}

// ---------------------------------------------------------------------------
// Kernel 2: broadcast. Each block = 128 threads = one row of float4s for
// batch b; block covers ROWS consecutive n positions. Load once, store ROWS
// times (independent STG.128 -> high ILP, warp-contiguous addresses).
// ---------------------------------------------------------------------------
#define ROWS 16

__global__ void __launch_bounds__(128)
broadcast_rows(float4* __restrict__ out)
{
    const unsigned j     = threadIdx.x;            // float4 index within row
    const unsigned blk   = blockIdx.x;             // 0 .. 8*(4096/ROWS)-1
    const unsigned tiles = N_PTS / ROWS;           // 256 tiles per batch
    const unsigned b     = blk / tiles;
    const unsigned n0    = (blk % tiles) * ROWS;

    const float4 val = __ldg(&g_rowvec4[b * 128 + j]);

    float4* base = out + (size_t)(b * N_PTS + n0) * 128 + j;
    #pragma unroll
    for (int r = 0; r < ROWS; ++r)
        base[r * 128] = val;
}

// ---------------------------------------------------------------------------
extern "C" void kernel_launch(void* const* d_in, const int* in_sizes, int n_in,
                              void* d_out, int out_size)
{
    const float* g  = (const float*)d_in[1];
    const float* Wv = (const float*)d_in[6];
    const float* bv = (const float*)d_in[7];
    const float* Wo = (const float*)d_in[8];
    const float* bo = (const float*)d_in[9];

    compute_row_vectors<<<B_SZ, 512>>>(g, Wv, bv, Wo, bo);

    const unsigned nblocks = B_SZ * (N_PTS / ROWS);   // 2048
    broadcast_rows<<<nblocks, 128>>>(reinterpret_cast<float4*>(d_out));
}